// round 16
// baseline (speedup 1.0000x reference)
#include <cuda_runtime.h>
#include <cuda_fp16.h>
#include <cstdint>

#define T_LEN 16384
#define BATCH 4
#define CRES 128
#define NBLK 40
#define SKIPLEN 4096
#define SKIPSTART (T_LEN - SKIPLEN)

#define THREADS 256
#define TT 64

// SMEM layout (bytes) — XOR-swizzled, zero padding
#define SM_XD  0            // 64 rows x 256B fp16 (Xd / G)
#define SM_XC  16384        // 64 rows x 256B fp16 (Xc)
#define SM_W0  32768        // 16KB K-chunk buffer 0 (128 rows x 128B)
#define SM_W1  49152        // 16KB K-chunk buffer 1
#define SM_TOTAL 65536

// ---------------- device scratch ----------------
__device__ float g_actA[(size_t)BATCH * T_LEN * CRES];
__device__ float g_actB[(size_t)BATCH * T_LEN * CRES];
__device__ __align__(16) __half g_mirA[(size_t)BATCH * T_LEN * CRES];
__device__ __align__(16) __half g_mirB[(size_t)BATCH * T_LEN * CRES];
// gate-output (G) parity buffers for the skip window: [b][4096][128] fp16
__device__ __align__(16) __half g_gA[(size_t)BATCH * SKIPLEN * CRES];
__device__ __align__(16) __half g_gB[(size_t)BATCH * SKIPLEN * CRES];
// per block: 5 matrices x 2 K-chunks x 8192 fp16 (16KB).
// chunk index = m*2 + c;  m: 0=wd tap0, 1=wd tap1, 2=wres, 3=wskA, 4=wskB
__device__ __align__(16) __half g_wimg[(size_t)NBLK * 10 * 8192];

// ---------------- helpers ----------------
__device__ __forceinline__ uint32_t smem_u32(const void* p) {
    uint32_t a;
    asm("{ .reg .u64 t; cvta.to.shared.u64 t, %1; cvt.u32.u64 %0, t; }" : "=r"(a) : "l"(p));
    return a;
}
__device__ __forceinline__ void ldsm4(uint32_t* r, uint32_t addr) {
    asm volatile("ldmatrix.sync.aligned.m8n8.x4.shared.b16 {%0,%1,%2,%3}, [%4];"
                 : "=r"(r[0]), "=r"(r[1]), "=r"(r[2]), "=r"(r[3]) : "r"(addr));
}
__device__ __forceinline__ void mma16816(float* d, const uint32_t* a, const uint32_t* b) {
    asm volatile("mma.sync.aligned.m16n8k16.row.col.f32.f16.f16.f32 "
                 "{%0,%1,%2,%3},{%4,%5,%6,%7},{%8,%9},{%0,%1,%2,%3};"
                 : "+f"(d[0]), "+f"(d[1]), "+f"(d[2]), "+f"(d[3])
                 : "r"(a[0]), "r"(a[1]), "r"(a[2]), "r"(a[3]), "r"(b[0]), "r"(b[1]));
}
__device__ __forceinline__ void cpa16(uint32_t dst, const void* src) {
    asm volatile("cp.async.cg.shared.global [%0], [%1], 16;" :: "r"(dst), "l"(src));
}
__device__ __forceinline__ void cpa16z(uint32_t dst, const void* src, uint32_t n) {
    asm volatile("cp.async.cg.shared.global [%0], [%1], 16, %2;"
                 :: "r"(dst), "l"(src), "r"(n));
}
#define CP_COMMIT()  asm volatile("cp.async.commit_group;" ::: "memory")
#define CP_WAITG(n)  asm volatile("cp.async.wait_group %0;" :: "n"(n) : "memory")

__device__ __forceinline__ uint32_t pack_h2(float x0, float x1) {
    __half2 h = __floats2half2_rn(x0, x1);
    return *reinterpret_cast<uint32_t*>(&h);
}
__device__ __forceinline__ float gate_fn(float h) {
    h = fminf(fmaxf(h, -30.f), 30.f);
    float e = __expf(-h);
    float e2 = e * e;
    return __fdividef(1.f - e2, (1.f + e2) * (1.f + e));
}

// ---------------- pre-pass kernels ----------------
__global__ void transpose_x(const float* __restrict__ x, float* __restrict__ xt,
                            __half* __restrict__ xh) {
    __shared__ float tile[32][33];
    int b = blockIdx.z, c0 = blockIdx.y * 32, t0 = blockIdx.x * 32;
    int lx = threadIdx.x, ly = threadIdx.y;
    #pragma unroll
    for (int i = 0; i < 32; i += 8)
        tile[ly + i][lx] = x[((size_t)b * CRES + c0 + ly + i) * T_LEN + t0 + lx];
    __syncthreads();
    #pragma unroll
    for (int i = 0; i < 32; i += 8) {
        float v = tile[lx][ly + i];
        size_t idx = ((size_t)b * T_LEN + t0 + ly + i) * CRES + c0 + lx;
        xt[idx] = v;
        xh[idx] = __float2half_rn(v);
    }
}

__global__ void prep_weights(const float* __restrict__ wd, const float* __restrict__ wr,
                             const float* __restrict__ wsk, __half* __restrict__ img) {
    int blk = blockIdx.x, m = blockIdx.y;
    for (int e = threadIdx.x; e < 16384; e += 256) {
        int o = e >> 7, k = e & 127;
        float v;
        if      (m == 0) v = wd[((size_t)blk * 16384 + o * 128 + k) * 2 + 0];
        else if (m == 1) v = wd[((size_t)blk * 16384 + o * 128 + k) * 2 + 1];
        else if (m == 2) v = wr[(size_t)blk * 16384 + o * 128 + k];
        else if (m == 3) v = wsk[(size_t)blk * 32768 + o * 128 + k];
        else             v = wsk[(size_t)blk * 32768 + (o + 128) * 128 + k];
        int c = k >> 6, kl = k & 63;
        size_t base = (size_t)blk * 81920 + (size_t)(m * 2 + c) * 8192;
        img[base + o * 64 + kl] = __float2half_rn(v);
    }
}

// ---------------- fused main + deferred-skip kernel ----------------
__global__ void __launch_bounds__(THREADS, 3)
wnet_mma(const float* __restrict__ in, const __half* __restrict__ mirin,
         float* __restrict__ resout, __half* __restrict__ mirout,
         const __half* __restrict__ img, __half* __restrict__ gout,
         const __half* __restrict__ imgprev, const __half* __restrict__ gin,
         float* __restrict__ skipprev, int dil, int main_bxs)
{
    extern __shared__ char smem[];
    const uint32_t sb = smem_u32(smem);
    const int tid = threadIdx.x;
    const int lane = tid & 31, wid = tid >> 5;
    const int wm = wid & 1;        // 2 M groups (32 t rows each)
    const int wn = wid >> 1;       // 4 N groups (32 out cols each)
    const int bx = blockIdx.x;
    const int b = blockIdx.y;

    // A-side ldmatrix constants (256B rows, 16 chunks)
    const uint32_t arow = (uint32_t)(wm * 32 + (lane & 15)) * 256;
    const uint32_t rxa  = (uint32_t)(lane & 7) << 4;
    const uint32_t kla  = (uint32_t)(lane >> 4) << 4;
    // B-side ldmatrix constants (128B rows, 8 chunks)
    const uint32_t brow = (uint32_t)(wn * 32 + (lane & 7) + ((lane >> 4) << 3)) * 128;
    const uint32_t rxb  = (uint32_t)(lane & 7) << 4;
    const uint32_t klb  = (uint32_t)((lane >> 3) & 1) << 4;

    // ---- shared lambdas ----
    auto load_img = [&](const __half* base, int cidx, uint32_t wslot) {
        const char* g = (const char*)(base + (size_t)cidx * 8192);
        #pragma unroll
        for (int i = 0; i < 4; ++i) {
            uint32_t e = (uint32_t)tid + i * THREADS;      // 0..1023 16B chunks
            uint32_t row = e >> 3, k = e & 7;
            cpa16(sb + wslot + row * 128 + ((k ^ (row & 7)) << 4), g + (size_t)e * 16);
        }
        CP_COMMIT();
    };

    float acc[2][4][4];
    auto zero_acc = [&]() {
        #pragma unroll
        for (int mt = 0; mt < 2; ++mt)
            #pragma unroll
            for (int nt = 0; nt < 4; ++nt)
                #pragma unroll
                for (int j = 0; j < 4; ++j) acc[mt][nt][j] = 0.f;
    };

    auto gemm_chunk = [&](uint32_t aSlot, uint32_t wslot, int k0base) {
        #pragma unroll
        for (int k0l = 0; k0l < 4; ++k0l) {
            uint32_t aoffs = ((((uint32_t)(k0base + k0l)) * 32 + kla) ^ rxa);
            uint32_t boffs = (((uint32_t)k0l * 32 + klb) ^ rxb);
            uint32_t a[2][4], bb[2][4];
            ldsm4(a[0], sb + aSlot + arow + aoffs);
            ldsm4(a[1], sb + aSlot + arow + 4096 + aoffs);
            ldsm4(bb[0], sb + wslot + brow + boffs);
            ldsm4(bb[1], sb + wslot + brow + 2048 + boffs);
            #pragma unroll
            for (int mt = 0; mt < 2; ++mt)
                #pragma unroll
                for (int nt = 0; nt < 4; ++nt)
                    mma16816(acc[mt][nt], a[mt], &bb[nt >> 1][(nt & 1) * 2]);
        }
    };

    // ======================= SKIP role (deferred from previous layer) =======================
    if (bx >= main_bxs) {
        const int sx = bx - main_bxs;                  // 0..63
        const __half* gsrc = gin + ((size_t)b * SKIPLEN + (size_t)sx * TT) * CRES;

        // load G tile (16KB) + weight chunks 6,7
        #pragma unroll
        for (int i = 0; i < 4; ++i) {
            uint32_t e = (uint32_t)tid + i * THREADS;
            uint32_t row = e >> 4, k = e & 15;
            cpa16(sb + SM_XD + row * 256 + ((k ^ (row & 7)) << 4),
                  (const char*)(gsrc + (size_t)row * CRES) + k * 16);
        }
        CP_COMMIT();
        load_img(imgprev, 6, SM_W0);
        load_img(imgprev, 7, SM_W1);
        CP_WAITG(0);
        __syncthreads();

        auto store_skip = [&](int half) {
            float* sd = skipprev + ((size_t)b * 256 + half * 128) * SKIPLEN + sx * TT;
            #pragma unroll
            for (int mt = 0; mt < 2; ++mt)
                #pragma unroll
                for (int nt = 0; nt < 4; ++nt) {
                    int c = wn * 32 + nt * 8 + (lane & 3) * 2;
                    #pragma unroll
                    for (int h = 0; h < 2; ++h) {
                        int r = wm * 32 + mt * 16 + (lane >> 2) + h * 8;
                        sd[(size_t)c * SKIPLEN + r]       = acc[mt][nt][h * 2 + 0];
                        sd[(size_t)(c + 1) * SKIPLEN + r] = acc[mt][nt][h * 2 + 1];
                    }
                }
        };

        zero_acc();
        gemm_chunk(SM_XD, SM_W0, 0);       // wskA c0
        __syncthreads();                   // W0 consumed by all warps
        load_img(imgprev, 8, SM_W0);
        gemm_chunk(SM_XD, SM_W1, 4);       // wskA c1
        __syncthreads();                   // W1 consumed
        load_img(imgprev, 9, SM_W1);
        store_skip(0);
        CP_WAITG(1);                       // chunk 8 resident
        __syncthreads();
        zero_acc();
        gemm_chunk(SM_XD, SM_W0, 0);       // wskB c0
        CP_WAITG(0);                       // chunk 9 resident
        __syncthreads();
        gemm_chunk(SM_XD, SM_W1, 4);       // wskB c1
        store_skip(1);
        return;
    }

    // ======================= MAIN role (uniform, 6 chunks) =======================
    const int t0 = bx * TT;
    const bool heavy = (t0 >= SKIPSTART);
    const float*  src  = in    + (size_t)b * T_LEN * CRES;
    const __half* msrc = mirin + (size_t)b * T_LEN * CRES;

    auto loadA = [&](uint32_t slot, bool shifted) {
        #pragma unroll
        for (int i = 0; i < 4; ++i) {
            uint32_t e = (uint32_t)tid + i * THREADS;
            uint32_t row = e >> 4, k = e & 15;
            int ts = shifted ? (t0 + (int)row - dil) : (t0 + (int)row);
            const char* s = (const char*)(msrc + (size_t)(ts < 0 ? 0 : ts) * CRES) + k * 16;
            uint32_t dst = sb + slot + row * 256 + ((k ^ (row & 7)) << 4);
            cpa16z(dst, s, ts >= 0 ? 16u : 0u);
        }
        CP_COMMIT();
    };

    loadA(SM_XD, true);                  // Xd (shifted)
    loadA(SM_XC, false);                 // Xc
    load_img(img, 0, SM_W0);
    load_img(img, 1, SM_W1);
    CP_WAITG(1);
    __syncthreads();

    // ---- phase 1: h = Wd0 @ Xd + Wd1 @ Xc ----
    zero_acc();
    gemm_chunk(SM_XD, SM_W0, 0);
    CP_WAITG(0); __syncthreads(); load_img(img, 2, SM_W0);
    gemm_chunk(SM_XD, SM_W1, 4);
    CP_WAITG(0); __syncthreads(); load_img(img, 3, SM_W1);
    gemm_chunk(SM_XC, SM_W0, 0);
    CP_WAITG(0); __syncthreads(); load_img(img, 4, SM_W0);
    gemm_chunk(SM_XC, SM_W1, 4);
    CP_WAITG(0); __syncthreads();
    load_img(img, 5, SM_W1);             // wres c1 overlaps gate

    // ---- gate -> G into XD slot; heavy: also STG G to parity buffer ----
    __half* gdst = gout + ((size_t)b * SKIPLEN + (t0 - SKIPSTART)) * CRES;
    #pragma unroll
    for (int mt = 0; mt < 2; ++mt)
        #pragma unroll
        for (int nt = 0; nt < 4; ++nt) {
            int c = wn * 32 + nt * 8 + (lane & 3) * 2;
            #pragma unroll
            for (int h = 0; h < 2; ++h) {
                int r = wm * 32 + mt * 16 + (lane >> 2) + h * 8;
                float g0 = gate_fn(acc[mt][nt][h * 2 + 0]);
                float g1 = gate_fn(acc[mt][nt][h * 2 + 1]);
                uint32_t hl = pack_h2(g0, g1);
                uint32_t off = (uint32_t)r * 256
                             + (uint32_t)((((c >> 3) ^ (r & 7)) << 4) + (c & 7) * 2);
                *(uint32_t*)(smem + SM_XD + off) = hl;
                if (heavy) *(uint32_t*)(gdst + (size_t)r * CRES + c) = hl;
            }
        }
    zero_acc();
    __syncthreads();                     // G visible CTA-wide

    // ---- phase 2: res = Wres @ G ----
    gemm_chunk(SM_XD, SM_W0, 0);
    CP_WAITG(0); __syncthreads();
    gemm_chunk(SM_XD, SM_W1, 4);

    // ---- residual epilogue: out = acc + Xc(global fp32); also fp16 mirror ----
    {
        float*  dst  = resout + ((size_t)b * T_LEN + t0) * CRES;
        __half* mdst = mirout + ((size_t)b * T_LEN + t0) * CRES;
        const float* xc = src + (size_t)t0 * CRES;
        #pragma unroll
        for (int mt = 0; mt < 2; ++mt)
            #pragma unroll
            for (int nt = 0; nt < 4; ++nt) {
                int c = wn * 32 + nt * 8 + (lane & 3) * 2;
                #pragma unroll
                for (int h = 0; h < 2; ++h) {
                    int r = wm * 32 + mt * 16 + (lane >> 2) + h * 8;
                    float2 x = *(const float2*)(xc + (size_t)r * CRES + c);
                    float2 o;
                    o.x = acc[mt][nt][h * 2 + 0] + x.x;
                    o.y = acc[mt][nt][h * 2 + 1] + x.y;
                    *(float2*)(dst + (size_t)r * CRES + c) = o;
                    *(uint32_t*)(mdst + (size_t)r * CRES + c) = pack_h2(o.x, o.y);
                }
            }
    }
}

// ---------------- host ----------------
extern "C" void kernel_launch(void* const* d_in, const int* in_sizes, int n_in,
                              void* d_out, int out_size)
{
    const float* x      = (const float*)d_in[0];
    const float* w_dil  = (const float*)d_in[1];
    const float* w_res  = (const float*)d_in[2];
    const float* w_skip = (const float*)d_in[3];
    float* out = (float*)d_out;

    float *pA, *pB;
    __half *pMA, *pMB, *pGA, *pGB, *pimg;
    cudaGetSymbolAddress((void**)&pA, g_actA);
    cudaGetSymbolAddress((void**)&pB, g_actB);
    cudaGetSymbolAddress((void**)&pMA, g_mirA);
    cudaGetSymbolAddress((void**)&pMB, g_mirB);
    cudaGetSymbolAddress((void**)&pGA, g_gA);
    cudaGetSymbolAddress((void**)&pGB, g_gB);
    cudaGetSymbolAddress((void**)&pimg, g_wimg);

    cudaFuncSetAttribute(wnet_mma, cudaFuncAttributeMaxDynamicSharedMemorySize, SM_TOTAL);

    transpose_x<<<dim3(T_LEN / 32, CRES / 32, BATCH), dim3(32, 8)>>>(x, pA, pMA);
    prep_weights<<<dim3(NBLK, 5), 256>>>(w_dil, w_res, w_skip, pimg);

    for (int i = 0; i < NBLK; ++i) {
        const float*  srcp = (i & 1) ? pB : pA;
        float*        dstp = (i & 1) ? pA : pB;
        const __half* msrc = (i & 1) ? pMB : pMA;
        __half*       mdst = (i & 1) ? pMA : pMB;
        __half*       gout = (i & 1) ? pGB : pGA;
        int prev = (i > 0) ? (i - 1) : 0;
        const __half* gin  = (prev & 1) ? pGB : pGA;
        int gridx = (i == 0) ? 256 : 320;
        wnet_mma<<<dim3(gridx, BATCH), THREADS, SM_TOTAL>>>(
            srcp, msrc, dstp, mdst,
            pimg + (size_t)i * 81920, gout,
            pimg + (size_t)prev * 81920, gin,
            out + (size_t)prev * BATCH * 256 * SKIPLEN,
            1 << (i % 10), 256);
    }
    // epilogue: drain layer 39's skip
    {
        const float*  srcp = pB;  float* dstp = pA;
        const __half* msrc = pMB; __half* mdst = pMA;
        wnet_mma<<<dim3(64, BATCH), THREADS, SM_TOTAL>>>(
            srcp, msrc, dstp, mdst,
            pimg + (size_t)39 * 81920, pGA,
            pimg + (size_t)39 * 81920, pGB,
            out + (size_t)39 * BATCH * 256 * SKIPLEN,
            1, 0);
    }
}

// round 17
// speedup vs baseline: 1.0468x; 1.0468x over previous
#include <cuda_runtime.h>
#include <cuda_fp16.h>
#include <cstdint>

#define T_LEN 16384
#define BATCH 4
#define CRES 128
#define NBLK 40
#define SKIPLEN 4096
#define SKIPSTART (T_LEN - SKIPLEN)

#define THREADS 256
#define TT 64

// SMEM layout (bytes) — XOR-swizzled, zero padding
#define SM_XD  0            // 64 rows x 256B fp16 (Xd, later G)
#define SM_XC  16384        // 64 rows x 256B fp16 (Xc)
#define SM_W0  32768        // 16KB K-chunk buffer 0 (128 rows x 128B)
#define SM_W1  49152        // 16KB K-chunk buffer 1
#define SM_TOTAL 65536

// ---------------- device scratch ----------------
__device__ float g_actA[(size_t)BATCH * T_LEN * CRES];
__device__ float g_actB[(size_t)BATCH * T_LEN * CRES];
__device__ __align__(16) __half g_mirA[(size_t)BATCH * T_LEN * CRES];
__device__ __align__(16) __half g_mirB[(size_t)BATCH * T_LEN * CRES];
// per block: 5 matrices x 2 K-chunks x 8192 fp16 (16KB).
// chunk index = m*2 + c;  m: 0=wd tap0, 1=wd tap1, 2=wres, 3=wskA, 4=wskB
__device__ __align__(16) __half g_wimg[(size_t)NBLK * 10 * 8192];

// ---------------- helpers ----------------
__device__ __forceinline__ uint32_t smem_u32(const void* p) {
    uint32_t a;
    asm("{ .reg .u64 t; cvta.to.shared.u64 t, %1; cvt.u32.u64 %0, t; }" : "=r"(a) : "l"(p));
    return a;
}
__device__ __forceinline__ void ldsm4(uint32_t* r, uint32_t addr) {
    asm volatile("ldmatrix.sync.aligned.m8n8.x4.shared.b16 {%0,%1,%2,%3}, [%4];"
                 : "=r"(r[0]), "=r"(r[1]), "=r"(r[2]), "=r"(r[3]) : "r"(addr));
}
__device__ __forceinline__ void mma16816(float* d, const uint32_t* a, const uint32_t* b) {
    asm volatile("mma.sync.aligned.m16n8k16.row.col.f32.f16.f16.f32 "
                 "{%0,%1,%2,%3},{%4,%5,%6,%7},{%8,%9},{%0,%1,%2,%3};"
                 : "+f"(d[0]), "+f"(d[1]), "+f"(d[2]), "+f"(d[3])
                 : "r"(a[0]), "r"(a[1]), "r"(a[2]), "r"(a[3]), "r"(b[0]), "r"(b[1]));
}
__device__ __forceinline__ void cpa16(uint32_t dst, const void* src) {
    asm volatile("cp.async.cg.shared.global [%0], [%1], 16;" :: "r"(dst), "l"(src));
}
__device__ __forceinline__ void cpa16z(uint32_t dst, const void* src, uint32_t n) {
    asm volatile("cp.async.cg.shared.global [%0], [%1], 16, %2;"
                 :: "r"(dst), "l"(src), "r"(n));
}
#define CP_COMMIT()  asm volatile("cp.async.commit_group;" ::: "memory")
#define CP_WAITG(n)  asm volatile("cp.async.wait_group %0;" :: "n"(n) : "memory")

__device__ __forceinline__ void stg_cs(float* p, float v) {
    asm volatile("st.global.cs.f32 [%0], %1;" :: "l"(p), "f"(v) : "memory");
}

__device__ __forceinline__ uint32_t pack_h2(float x0, float x1) {
    __half2 h = __floats2half2_rn(x0, x1);
    return *reinterpret_cast<uint32_t*>(&h);
}
__device__ __forceinline__ float gate_fn(float h) {
    h = fminf(fmaxf(h, -30.f), 30.f);
    float e = __expf(-h);
    float e2 = e * e;
    return __fdividef(1.f - e2, (1.f + e2) * (1.f + e));
}

// ---------------- pre-pass kernels ----------------
__global__ void transpose_x(const float* __restrict__ x, float* __restrict__ xt,
                            __half* __restrict__ xh) {
    __shared__ float tile[32][33];
    int b = blockIdx.z, c0 = blockIdx.y * 32, t0 = blockIdx.x * 32;
    int lx = threadIdx.x, ly = threadIdx.y;
    #pragma unroll
    for (int i = 0; i < 32; i += 8)
        tile[ly + i][lx] = x[((size_t)b * CRES + c0 + ly + i) * T_LEN + t0 + lx];
    __syncthreads();
    #pragma unroll
    for (int i = 0; i < 32; i += 8) {
        float v = tile[lx][ly + i];
        size_t idx = ((size_t)b * T_LEN + t0 + ly + i) * CRES + c0 + lx;
        xt[idx] = v;
        xh[idx] = __float2half_rn(v);
    }
}

__global__ void prep_weights(const float* __restrict__ wd, const float* __restrict__ wr,
                             const float* __restrict__ wsk, __half* __restrict__ img) {
    int blk = blockIdx.x, m = blockIdx.y;
    for (int e = threadIdx.x; e < 16384; e += 256) {
        int o = e >> 7, k = e & 127;
        float v;
        if      (m == 0) v = wd[((size_t)blk * 16384 + o * 128 + k) * 2 + 0];
        else if (m == 1) v = wd[((size_t)blk * 16384 + o * 128 + k) * 2 + 1];
        else if (m == 2) v = wr[(size_t)blk * 16384 + o * 128 + k];
        else if (m == 3) v = wsk[(size_t)blk * 32768 + o * 128 + k];
        else             v = wsk[(size_t)blk * 32768 + (o + 128) * 128 + k];
        int c = k >> 6, kl = k & 63;
        size_t base = (size_t)blk * 81920 + (size_t)(m * 2 + c) * 8192;
        img[base + o * 64 + kl] = __float2half_rn(v);
    }
}

// ---------------- main block kernel (R12 structure) ----------------
__global__ void __launch_bounds__(THREADS, 3)
wnet_mma(const float* __restrict__ in, const __half* __restrict__ mirin,
         float* __restrict__ resout, __half* __restrict__ mirout,
         const __half* __restrict__ img, float* __restrict__ skipout, int dil)
{
    extern __shared__ char smem[];
    const uint32_t sb = smem_u32(smem);
    const int tid = threadIdx.x;
    const int lane = tid & 31, wid = tid >> 5;
    const int wm = wid & 1;        // 2 M groups (32 t rows each)
    const int wn = wid >> 1;       // 4 N groups (32 out cols each)
    // heavy-first remap: skip CTAs launch first
    const int bx = (blockIdx.x + 192) & 255;
    const int b = blockIdx.y, t0 = bx * TT;
    const bool skip = (t0 >= SKIPSTART);

    // A-side ldmatrix constants (256B rows, 16 chunks)
    const uint32_t arow = (uint32_t)(wm * 32 + (lane & 15)) * 256;
    const uint32_t rxa  = (uint32_t)(lane & 7) << 4;
    const uint32_t kla  = (uint32_t)(lane >> 4) << 4;
    // B-side ldmatrix constants (128B rows, 8 chunks)
    const uint32_t brow = (uint32_t)(wn * 32 + (lane & 7) + ((lane >> 4) << 3)) * 128;
    const uint32_t rxb  = (uint32_t)(lane & 7) << 4;
    const uint32_t klb  = (uint32_t)((lane >> 3) & 1) << 4;

    const float*  src  = in    + (size_t)b * T_LEN * CRES;
    const __half* msrc = mirin + (size_t)b * T_LEN * CRES;

    // ---- 16KB K-chunk load (128 rows x 128B, swizzled) ----
    auto load_img = [&](int cidx, uint32_t wslot) {
        const char* g = (const char*)(img + (size_t)cidx * 8192);
        #pragma unroll
        for (int i = 0; i < 4; ++i) {
            uint32_t e = (uint32_t)tid + i * THREADS;      // 0..1023 16B chunks
            uint32_t row = e >> 3, k = e & 7;
            cpa16(sb + wslot + row * 128 + ((k ^ (row & 7)) << 4), g + (size_t)e * 16);
        }
        CP_COMMIT();
    };

    // ---- activation tile: cp.async fp16 mirror -> swizzled SMEM (zero-fill t<0) ----
    auto loadA = [&](uint32_t slot, bool shifted) {
        #pragma unroll
        for (int i = 0; i < 4; ++i) {
            uint32_t e = (uint32_t)tid + i * THREADS;      // 0..1023 16B chunks
            uint32_t row = e >> 4, k = e & 15;
            int ts = shifted ? (t0 + (int)row - dil) : (t0 + (int)row);
            const char* s = (const char*)(msrc + (size_t)(ts < 0 ? 0 : ts) * CRES) + k * 16;
            uint32_t dst = sb + slot + row * 256 + ((k ^ (row & 7)) << 4);
            cpa16z(dst, s, ts >= 0 ? 16u : 0u);
        }
        CP_COMMIT();
    };

    float acc[2][4][4];
    auto zero_acc = [&]() {
        #pragma unroll
        for (int mt = 0; mt < 2; ++mt)
            #pragma unroll
            for (int nt = 0; nt < 4; ++nt)
                #pragma unroll
                for (int j = 0; j < 4; ++j) acc[mt][nt][j] = 0.f;
    };

    // ---- one K-chunk GEMM (K=64, warp tile 32x32) ----
    auto gemm_chunk = [&](uint32_t aSlot, uint32_t wslot, int k0base) {
        #pragma unroll
        for (int k0l = 0; k0l < 4; ++k0l) {
            uint32_t aoffs = ((((uint32_t)(k0base + k0l)) * 32 + kla) ^ rxa);
            uint32_t boffs = (((uint32_t)k0l * 32 + klb) ^ rxb);
            uint32_t a[2][4], bb[2][4];
            ldsm4(a[0], sb + aSlot + arow + aoffs);
            ldsm4(a[1], sb + aSlot + arow + 4096 + aoffs);
            ldsm4(bb[0], sb + wslot + brow + boffs);
            ldsm4(bb[1], sb + wslot + brow + 2048 + boffs);
            #pragma unroll
            for (int mt = 0; mt < 2; ++mt)
                #pragma unroll
                for (int nt = 0; nt < 4; ++nt)
                    mma16816(acc[mt][nt], a[mt], &bb[nt >> 1][(nt & 1) * 2]);
        }
    };

    // ---- direct skip store (streaming, evict-first): acc -> skipout[o][t] ----
    auto store_skip = [&](int half) {
        float* sd = skipout + ((size_t)b * 256 + half * 128) * SKIPLEN + (t0 - SKIPSTART);
        #pragma unroll
        for (int mt = 0; mt < 2; ++mt)
            #pragma unroll
            for (int nt = 0; nt < 4; ++nt) {
                int c = wn * 32 + nt * 8 + (lane & 3) * 2;
                #pragma unroll
                for (int h = 0; h < 2; ++h) {
                    int r = wm * 32 + mt * 16 + (lane >> 2) + h * 8;
                    stg_cs(sd + (size_t)c * SKIPLEN + r,       acc[mt][nt][h * 2 + 0]);
                    stg_cs(sd + (size_t)(c + 1) * SKIPLEN + r, acc[mt][nt][h * 2 + 1]);
                }
            }
    };

    // ================= prologue =================
    loadA(SM_XD, true);                  // g0: Xd (shifted)
    loadA(SM_XC, false);                 // g1: Xc
    load_img(0, SM_W0);                  // g2
    load_img(1, SM_W1);                  // g3
    CP_WAITG(1);                         // XD, XC, chunk0 ready (chunk1 may lag)
    __syncthreads();

    zero_acc();
    gemm_chunk(SM_XD, SM_W0, 0);         // wd0 c0
    CP_WAITG(0); __syncthreads(); load_img(2, SM_W0);
    gemm_chunk(SM_XD, SM_W1, 4);         // wd0 c1
    CP_WAITG(0); __syncthreads(); load_img(3, SM_W1);
    gemm_chunk(SM_XC, SM_W0, 0);         // wd1 c0
    CP_WAITG(0); __syncthreads(); load_img(4, SM_W0);
    gemm_chunk(SM_XC, SM_W1, 4);         // wd1 c1
    CP_WAITG(0); __syncthreads();        // wres c0 resident; W1 & XD consumed
    load_img(5, SM_W1);                  // overlap wres c1 load with gate

    // ---- gate -> G into XD slot ----
    #pragma unroll
    for (int mt = 0; mt < 2; ++mt)
        #pragma unroll
        for (int nt = 0; nt < 4; ++nt) {
            int c = wn * 32 + nt * 8 + (lane & 3) * 2;
            #pragma unroll
            for (int h = 0; h < 2; ++h) {
                int r = wm * 32 + mt * 16 + (lane >> 2) + h * 8;
                float g0 = gate_fn(acc[mt][nt][h * 2 + 0]);
                float g1 = gate_fn(acc[mt][nt][h * 2 + 1]);
                uint32_t off = (uint32_t)r * 256
                             + (uint32_t)((((c >> 3) ^ (r & 7)) << 4) + (c & 7) * 2);
                *(uint32_t*)(smem + SM_XD + off) = pack_h2(g0, g1);
            }
        }
    zero_acc();
    __syncthreads();                     // G visible to all warps

    // ---- phase 2: res = Wres @ G ----
    gemm_chunk(SM_XD, SM_W0, 0);         // wres c0
    CP_WAITG(0); __syncthreads(); if (skip) load_img(6, SM_W0);
    gemm_chunk(SM_XD, SM_W1, 4);         // wres c1

    // ---- residual epilogue: out = acc + Xc(global fp32); also fp16 mirror ----
    {
        float*  dst  = resout + ((size_t)b * T_LEN + t0) * CRES;
        __half* mdst = mirout + ((size_t)b * T_LEN + t0) * CRES;
        const float* xc = src + (size_t)t0 * CRES;
        #pragma unroll
        for (int mt = 0; mt < 2; ++mt)
            #pragma unroll
            for (int nt = 0; nt < 4; ++nt) {
                int c = wn * 32 + nt * 8 + (lane & 3) * 2;
                #pragma unroll
                for (int h = 0; h < 2; ++h) {
                    int r = wm * 32 + mt * 16 + (lane >> 2) + h * 8;
                    float2 x = *(const float2*)(xc + (size_t)r * CRES + c);
                    float2 o;
                    o.x = acc[mt][nt][h * 2 + 0] + x.x;
                    o.y = acc[mt][nt][h * 2 + 1] + x.y;
                    *(float2*)(dst + (size_t)r * CRES + c) = o;
                    *(uint32_t*)(mdst + (size_t)r * CRES + c) = pack_h2(o.x, o.y);
                }
            }
    }
    if (!skip) return;

    // ================= skip phase =================
    CP_WAITG(0); __syncthreads(); load_img(7, SM_W1);
    zero_acc();
    gemm_chunk(SM_XD, SM_W0, 0);         // wskA c0
    CP_WAITG(0); __syncthreads(); load_img(8, SM_W0);
    gemm_chunk(SM_XD, SM_W1, 4);         // wskA c1
    store_skip(0);
    CP_WAITG(0); __syncthreads(); load_img(9, SM_W1);
    zero_acc();
    gemm_chunk(SM_XD, SM_W0, 0);         // wskB c0
    CP_WAITG(0); __syncthreads();
    gemm_chunk(SM_XD, SM_W1, 4);         // wskB c1
    store_skip(1);
}

// ---------------- host ----------------
extern "C" void kernel_launch(void* const* d_in, const int* in_sizes, int n_in,
                              void* d_out, int out_size)
{
    const float* x      = (const float*)d_in[0];
    const float* w_dil  = (const float*)d_in[1];
    const float* w_res  = (const float*)d_in[2];
    const float* w_skip = (const float*)d_in[3];
    float* out = (float*)d_out;

    float *pA, *pB;
    __half *pMA, *pMB, *pimg;
    cudaGetSymbolAddress((void**)&pA, g_actA);
    cudaGetSymbolAddress((void**)&pB, g_actB);
    cudaGetSymbolAddress((void**)&pMA, g_mirA);
    cudaGetSymbolAddress((void**)&pMB, g_mirB);
    cudaGetSymbolAddress((void**)&pimg, g_wimg);

    cudaFuncSetAttribute(wnet_mma, cudaFuncAttributeMaxDynamicSharedMemorySize, SM_TOTAL);

    transpose_x<<<dim3(T_LEN / 32, CRES / 32, BATCH), dim3(32, 8)>>>(x, pA, pMA);
    prep_weights<<<dim3(NBLK, 5), 256>>>(w_dil, w_res, w_skip, pimg);

    for (int i = 0; i < NBLK; ++i) {
        const float*  srcp = (i & 1) ? pB : pA;
        float*        dstp = (i & 1) ? pA : pB;
        const __half* msrc = (i & 1) ? pMB : pMA;
        __half*       mdst = (i & 1) ? pMA : pMB;
        wnet_mma<<<dim3(T_LEN / TT, BATCH), THREADS, SM_TOTAL>>>(
            srcp, msrc, dstp, mdst,
            pimg + (size_t)i * 81920,
            out + (size_t)i * BATCH * 256 * SKIPLEN,
            1 << (i % 10));
    }
}